// round 3
// baseline (speedup 1.0000x reference)
#include <cuda_runtime.h>
#include <stdint.h>

#define N_BITS 16

// Word-domain bitwise adder (inputs exactly {0x00000000, 0x3F800000}).
// Each thread owns one float4 (=4 bits of a row) from TWO rows (ITEMS=2),
// with all 4 loads issued up front for MLP, and the cross-lane carry scan
// (segmented Kogge-Stone over 4-lane segments) interleaved for both items.
__global__ void __launch_bounds__(256)
ripple_cla2_kernel(const uint4* __restrict__ x4,
                   const uint4* __restrict__ y4,
                   uint4* __restrict__ s4,
                   uint4* __restrict__ c4,
                   int stride)   // total threads = n4/2; item1 at gid+stride
{
    const int gid = blockIdx.x * blockDim.x + threadIdx.x;
    const int i0 = gid;
    const int i1 = gid + stride;

    // Front-batched loads: 4 independent LDG.128 in flight.
    const uint4 xa = __ldcs(x4 + i0);
    const uint4 ya = __ldcs(y4 + i0);
    const uint4 xb = __ldcs(x4 + i1);
    const uint4 yb = __ldcs(y4 + i1);

    const unsigned seg = threadIdx.x & 3;
    const unsigned lt1 = seg >= 1, lt2 = seg >= 2;

    // ---- per-bit p/g for both items ----
    unsigned ap0 = xa.x ^ ya.x, ag0 = xa.x & ya.x;
    unsigned ap1 = xa.y ^ ya.y, ag1 = xa.y & ya.y;
    unsigned ap2 = xa.z ^ ya.z, ag2 = xa.z & ya.z;
    unsigned ap3 = xa.w ^ ya.w, ag3 = xa.w & ya.w;

    unsigned bp0 = xb.x ^ yb.x, bg0 = xb.x & yb.x;
    unsigned bp1 = xb.y ^ yb.y, bg1 = xb.y & yb.y;
    unsigned bp2 = xb.z ^ yb.z, bg2 = xb.z & yb.z;
    unsigned bp3 = xb.w ^ yb.w, bg3 = xb.w & yb.w;

    // ---- 4-bit group G/P ----
    unsigned GA = ag3 | (ap3 & (ag2 | (ap2 & (ag1 | (ap1 & ag0)))));
    unsigned PA = ap0 & ap1 & ap2 & ap3;
    unsigned GB = bg3 | (bp3 & (bg2 | (bp2 & (bg1 | (bp1 & bg0)))));
    unsigned PB = bp0 & bp1 & bp2 & bp3;

    // ---- segmented Kogge-Stone (segments of 4 lanes), both items interleaved ----
    unsigned GAu = __shfl_up_sync(0xffffffffu, GA, 1);
    unsigned PAu = __shfl_up_sync(0xffffffffu, PA, 1);
    unsigned GBu = __shfl_up_sync(0xffffffffu, GB, 1);
    unsigned PBu = __shfl_up_sync(0xffffffffu, PB, 1);
    if (lt1) { GA = GA | (PA & GAu); PA = PA & PAu;
               GB = GB | (PB & GBu); PB = PB & PBu; }

    GAu = __shfl_up_sync(0xffffffffu, GA, 2);
    GBu = __shfl_up_sync(0xffffffffu, GB, 2);
    if (lt2) { GA = GA | (PA & GAu);
               GB = GB | (PB & GBu); }

    unsigned cinA = __shfl_up_sync(0xffffffffu, GA, 1);
    unsigned cinB = __shfl_up_sync(0xffffffffu, GB, 1);
    if (seg == 0) { cinA = 0u; cinB = 0u; }

    // ---- local 4-bit ripple + pack + store (item A) ----
    {
        const unsigned c0 = ag0 | (ap0 & cinA);
        const unsigned c1 = ag1 | (ap1 & c0);
        const unsigned c2 = ag2 | (ap2 & c1);
        const unsigned c3 = ag3 | (ap3 & c2);
        uint4 sv, cv;
        sv.x = ap0 ^ cinA; sv.y = ap1 ^ c0; sv.z = ap2 ^ c1; sv.w = ap3 ^ c2;
        cv.x = c0;         cv.y = c1;       cv.z = c2;       cv.w = c3;
        __stcs(s4 + i0, sv);
        __stcs(c4 + i0, cv);
    }
    // ---- item B ----
    {
        const unsigned c0 = bg0 | (bp0 & cinB);
        const unsigned c1 = bg1 | (bp1 & c0);
        const unsigned c2 = bg2 | (bp2 & c1);
        const unsigned c3 = bg3 | (bp3 & c2);
        uint4 sv, cv;
        sv.x = bp0 ^ cinB; sv.y = bp1 ^ c0; sv.z = bp2 ^ c1; sv.w = bp3 ^ c2;
        cv.x = c0;         cv.y = c1;       cv.z = c2;       cv.w = c3;
        __stcs(s4 + i1, sv);
        __stcs(c4 + i1, cv);
    }
}

extern "C" void kernel_launch(void* const* d_in, const int* in_sizes, int n_in,
                              void* d_out, int out_size)
{
    const uint4* x4 = (const uint4*)d_in[0];
    const uint4* y4 = (const uint4*)d_in[1];
    const int n_elems = in_sizes[0];             // BATCH * 16 floats
    const int n4 = n_elems / 4;                  // float4 count = BATCH*4 = 8388608

    unsigned* out = (unsigned*)d_out;
    uint4* s4 = (uint4*)out;
    uint4* c4 = (uint4*)(out + (size_t)n_elems);

    const int threads = 256;
    const int total = n4 / 2;                    // 2 items per thread
    const int blocks = total / threads;          // divides exactly (4194304/256)
    ripple_cla2_kernel<<<blocks, threads>>>(x4, y4, s4, c4, total);
}